// round 17
// baseline (speedup 1.0000x reference)
#include <cuda_runtime.h>
#include <cuda_fp16.h>
#include <mma.h>
#include <cstdint>

using namespace nvcuda;

#define EPS 1e-5f

// Scratch (no cudaMalloc allowed). Feature maps TRANSPOSED: [spatial][bc]
__device__ __align__(16) float    g_zfT[196 * 16384];           // 12.8 MB
__device__ __align__(16) float    g_xfT[900 * 16384];           // 59 MB
__device__ __align__(16) __half   g_zp[64 * 16 * 16 * 256];     // fp16 z NHWC
__device__ __align__(16) __half   g_xp[64 * 32 * 32 * 256];     // fp16 x NHWC
__device__ __align__(16) __half   g_wz[256 * 2304];             // fp16 w_z tap-major
__device__ __align__(16) __half   g_wx[256 * 2304];             // fp16 w_x tap-major

__device__ __forceinline__ uint32_t smem_u32(const void* p) {
    uint32_t a;
    asm("{ .reg .u64 t; cvta.to.shared.u64 t, %1; cvt.u32.u64 %0, t; }"
        : "=r"(a) : "l"(p));
    return a;
}

#define CP_ASYNC16(dst, src) \
    asm volatile("cp.async.cg.shared.global [%0], [%1], 16;" \
        :: "r"(dst), "l"(src) : "memory")
#define CP_COMMIT() asm volatile("cp.async.commit_group;" ::: "memory")
#define CP_WAIT0()  asm volatile("cp.async.wait_group 0;" ::: "memory")

// ===========================================================================
// Pack input fp32 NCHW -> fp16 NHWC (smem-tiled transpose, conflict-free).
// ===========================================================================
template <int H, int W>
__global__ __launch_bounds__(256)
void pack_nhwc(const float* __restrict__ src, __half* __restrict__ dst)
{
    __shared__ __half sm[32 * 258];   // [w][c], fp16 stride 258 (bank-safe)
    const int bh   = blockIdx.x;      // b*H + h
    const int b    = bh / H;
    const int h    = bh - b * H;
    const int tid  = threadIdx.x;
    const int wid  = tid >> 5;
    const int lane = tid & 31;

#pragma unroll 4
    for (int c = wid; c < 256; c += 8) {
        if (lane < W) {
            float v = __ldg(src + (((size_t)b * 256 + c) * H + h) * W + lane);
            sm[lane * 258 + c] = __float2half_rn(v);
        }
    }
    __syncthreads();

    const int w  = tid >> 3;
    const int c0 = (tid & 7) << 5;
    if (w < W) {
        __half* dp = dst + (((size_t)bh) * W + w) * 256 + c0;
        uint32_t tmp[16];
#pragma unroll
        for (int i = 0; i < 16; i++) {
            __half2 hh = __halves2half2(sm[w * 258 + c0 + 2 * i],
                                        sm[w * 258 + c0 + 2 * i + 1]);
            tmp[i] = *reinterpret_cast<uint32_t*>(&hh);
        }
#pragma unroll
        for (int i = 0; i < 4; i++)
            reinterpret_cast<uint4*>(dp)[i] =
                make_uint4(tmp[4 * i], tmp[4 * i + 1], tmp[4 * i + 2], tmp[4 * i + 3]);
    }
}

// ---- pack weights fp32 [m][ci*9+r9] -> fp16 tap-major [m][r9*256+ci] ----
__global__ void pack_wT(const float* __restrict__ src, __half* __restrict__ dst)
{
    int i = blockIdx.x * blockDim.x + threadIdx.x;   // over 256*2304
    if (i >= 256 * 2304) return;
    int m  = i / 2304;
    int kp = i - m * 2304;
    int r9 = kp >> 8;
    int ci = kp & 255;
    dst[i] = __float2half_rn(__ldg(src + m * 2304 + ci * 9 + r9));
}

// ===========================================================================
// Implicit-GEMM 3x3 conv + fused BN, single-pass fp16 wmma, NHWC B path.
// BM=128, BN=128, BK=64, 128 threads / 4 warps, warp tile 64x64 (acc 4x4),
// MMA:LDSM = 2.0. Both fills cp.async, double-buffered. 2 CTAs/SM.
// ===========================================================================
template <int OH, int OW, int IH, int IW>
__global__ __launch_bounds__(128, 2)
void conv3x3_bn_wmma(const __half* __restrict__ xph,   // fp16 NHWC [B,IH,IW,256]
                     const __half* __restrict__ whalf, // fp16 [256][2304] tap-major
                     const float* __restrict__ gamma,
                     const float* __restrict__ beta,
                     const float* __restrict__ mean,
                     const float* __restrict__ var,
                     float* __restrict__ outT)         // [OH*OW][64*256]
{
    constexpr int C = 256, K = C * 9;
    constexpr int BM = 128, BN = 128, BK = 64;
    constexpr int NCH = K / BK;                 // 36 (4 chunks per tap)
    constexpr int OHW = OH * OW;
    constexpr int LDA = 72;                     // fp16 elems/row (144 B)
    constexpr int LDC = 132;
    constexpr uint32_t A_T = BM * LDA * 2;      // 18432
    constexpr uint32_t B_T = BN * LDA * 2;      // 18432
    constexpr uint32_t OF_B = 2 * A_T;          // 36864
    // total smem = 73728

    extern __shared__ char smem[];
    const uint32_t sbase = smem_u32(smem);

    const int tid = threadIdx.x;
    const int wid = tid >> 5;                   // 0..3
    const int n0 = blockIdx.x * BN;
    const int m0 = blockIdx.y * BM;
    const int wm = (wid >> 1) * 64;             // 2 m-warps
    const int wn = (wid & 1) * 64;              // 2 n-warps

    // --- A fill (cp.async): 8 chunks, chunk i: row r0+16i, 16B sub q ---
    const int r0 = tid >> 3;            // 0..15
    const int q  = tid & 7;             // 0..7
    const __half* whp = whalf + (size_t)(m0 + r0) * K + q * 8;
    const uint32_t ad0 = (uint32_t)(r0 * 144 + q * 16);

    // --- B fill (cp.async): one n per thread, all 64 k-channels (128 B) ---
    const int n     = n0 + tid;
    const int b_    = n / OHW;
    const int rem   = n - b_ * OHW;
    const int ohh   = rem / OW;
    const int oww   = rem - ohh * OW;
    const __half* xbT = xph + (size_t)b_ * IH * IW * 256;
    const uint32_t bd0 = (uint32_t)(tid * 144);

    auto fillA = [&](int ch) {
        const uint32_t s = sbase + (uint32_t)(ch & 1) * A_T + ad0;
        const int ko = ch * BK;
#pragma unroll
        for (int i = 0; i < 8; i++)
            CP_ASYNC16(s + i * 2304u, whp + ko + (size_t)i * 16 * K);
    };

    auto fillB = [&](int ch) {
        const int r9 = ch >> 2;                       // tap 0..8
        const int kh = r9 / 3, kw = r9 - kh * 3;
        const int ci0 = (ch & 3) << 6;                // 0,64,128,192
        const __half* p = xbT +
            ((size_t)((ohh + kh) * IW + (oww + kw))) * 256 + ci0;
        const uint32_t s = sbase + OF_B + (uint32_t)(ch & 1) * B_T + bd0;
#pragma unroll
        for (int j = 0; j < 8; j++)
            CP_ASYNC16(s + j * 16u, p + j * 8);
    };

    wmma::fragment<wmma::accumulator, 16, 16, 16, float> acc[4][4];
#pragma unroll
    for (int i = 0; i < 4; i++)
#pragma unroll
        for (int j = 0; j < 4; j++) wmma::fill_fragment(acc[i][j], 0.0f);

    // prologue: stage 0
    fillA(0);
    fillB(0);
    CP_COMMIT();

#pragma unroll 1
    for (int ch = 0; ch < NCH; ch++) {
        CP_WAIT0();
        __syncthreads();

        if (ch + 1 < NCH) {
            fillA(ch + 1);
            fillB(ch + 1);
            CP_COMMIT();               // lands during the MMA section below
        }

        const int buf = ch & 1;
        const __half* sa = (const __half*)(smem + buf * A_T);
        const __half* sb = (const __half*)(smem + OF_B + buf * B_T);

#pragma unroll
        for (int ks = 0; ks < 4; ks++) {
            const int ko = ks * 16;
            wmma::fragment<wmma::matrix_b, 16, 16, 16, __half, wmma::col_major> b[4];
#pragma unroll
            for (int j = 0; j < 4; j++)
                wmma::load_matrix_sync(b[j], sb + (wn + j * 16) * LDA + ko, LDA);
#pragma unroll
            for (int i = 0; i < 4; i++) {
                wmma::fragment<wmma::matrix_a, 16, 16, 16, __half, wmma::row_major> a;
                wmma::load_matrix_sync(a, sa + (wm + i * 16) * LDA + ko, LDA);
#pragma unroll
                for (int j = 0; j < 4; j++)
                    wmma::mma_sync(acc[i][j], a, b[j], acc[i][j]);
            }
        }
    }

    // ---- epilogue: acc -> SMEM C tile -> BN -> TRANSPOSED coalesced store ----
    __syncthreads();
    float* ct = (float*)smem;                   // 128 x 132 fp32 = 67584 B
#pragma unroll
    for (int i = 0; i < 4; i++)
#pragma unroll
        for (int j = 0; j < 4; j++)
            wmma::store_matrix_sync(ct + (wm + i * 16) * LDC + wn + j * 16,
                                    acc[i][j], LDC, wmma::mem_row_major);
    __syncthreads();

    // channel c = m0 + tid; 128 spatial positions; fully coalesced stores.
    {
        const int c = m0 + tid;
        const float sc = __ldg(&gamma[c]) * rsqrtf(__ldg(&var[c]) + EPS);
        const float bi = __ldg(&beta[c]) - __ldg(&mean[c]) * sc;
#pragma unroll 1
        for (int it = 0; it < 128; it++) {
            const int nn = n0 + it;
            const int b2 = nn / OHW;
            const int s  = nn - b2 * OHW;
            outT[((size_t)s * 64 + b2) * 256 + c] = ct[tid * LDC + it] * sc + bi;
        }
    }
}

// ===========================================================================
// Depthwise cross-correlation on transposed features (bc fastest, coalesced).
// ===========================================================================
__global__ __launch_bounds__(256)
void xcorr_kernel(const float* __restrict__ zfT,  // [196][16384]
                  const float* __restrict__ xfT,  // [900][16384]
                  float* __restrict__ out)        // [16384][17][17]
{
    const int g  = blockIdx.x * blockDim.x + threadIdx.x;
    const int bc = g & 16383;
    const int oh = g >> 14;

    const float* zp = zfT + bc;
    const float* xp = xfT + bc;

    float acc[17];
#pragma unroll
    for (int j = 0; j < 17; j++) acc[j] = 0.f;

#pragma unroll 1
    for (int p = 0; p < 14; p++) {
        float xr[30];
#pragma unroll
        for (int t = 0; t < 30; t++)
            xr[t] = __ldg(xp + (size_t)((oh + p) * 30 + t) * 16384);
        float zr[14];
#pragma unroll
        for (int qq = 0; qq < 14; qq++)
            zr[qq] = __ldg(zp + (size_t)(p * 14 + qq) * 16384);
#pragma unroll
        for (int qq = 0; qq < 14; qq++) {
            float zv = zr[qq];
#pragma unroll
            for (int j = 0; j < 17; j++)
                acc[j] = fmaf(zv, xr[qq + j], acc[j]);
        }
    }

    float* op = out + (size_t)bc * 289 + oh * 17;
#pragma unroll
    for (int j = 0; j < 17; j++) op[j] = acc[j];
}

// ===========================================================================
extern "C" void kernel_launch(void* const* d_in, const int* in_sizes, int n_in,
                              void* d_out, int out_size)
{
    const float* z       = (const float*)d_in[0];
    const float* x       = (const float*)d_in[1];
    const float* w_z     = (const float*)d_in[2];
    const float* w_x     = (const float*)d_in[3];
    const float* gamma_z = (const float*)d_in[4];
    const float* beta_z  = (const float*)d_in[5];
    const float* mean_z  = (const float*)d_in[6];
    const float* var_z   = (const float*)d_in[7];
    const float* gamma_x = (const float*)d_in[8];
    const float* beta_x  = (const float*)d_in[9];
    const float* mean_x  = (const float*)d_in[10];
    const float* var_x   = (const float*)d_in[11];
    float* out = (float*)d_out;

    float *zfT, *xfT;
    __half *zp16, *xp16, *wz16, *wx16;
    cudaGetSymbolAddress((void**)&zfT, g_zfT);
    cudaGetSymbolAddress((void**)&xfT, g_xfT);
    cudaGetSymbolAddress((void**)&zp16, g_zp);
    cudaGetSymbolAddress((void**)&xp16, g_xp);
    cudaGetSymbolAddress((void**)&wz16, g_wz);
    cudaGetSymbolAddress((void**)&wx16, g_wx);

    constexpr int SMEM_BYTES = 73728;

    static cudaStream_t s2 = nullptr;
    static cudaEvent_t e_fork = nullptr, e_join = nullptr;
    if (!s2) {
        cudaFuncSetAttribute(conv3x3_bn_wmma<14, 14, 16, 16>,
                             cudaFuncAttributeMaxDynamicSharedMemorySize, SMEM_BYTES);
        cudaFuncSetAttribute(conv3x3_bn_wmma<30, 30, 32, 32>,
                             cudaFuncAttributeMaxDynamicSharedMemorySize, SMEM_BYTES);
        cudaStreamCreateWithFlags(&s2, cudaStreamNonBlocking);
        cudaEventCreateWithFlags(&e_fork, cudaEventDisableTiming);
        cudaEventCreateWithFlags(&e_join, cudaEventDisableTiming);
    }

    // ---- fork: x-chain on side stream, z-chain on capture (null) stream ----
    cudaEventRecord(e_fork, 0);
    cudaStreamWaitEvent(s2, e_fork, 0);

    // x chain (big): NHWC pack x, tap-major pack wx, conv_x
    {
        pack_nhwc<32, 32><<<64 * 32, 256, 0, s2>>>(x, xp16);
        pack_wT<<<(256 * 2304 + 255) / 256, 256, 0, s2>>>(w_x, wx16);
        conv3x3_bn_wmma<30, 30, 32, 32><<<dim3(450, 2), 128, SMEM_BYTES, s2>>>(
            xp16, wx16, gamma_x, beta_x, mean_x, var_x, xfT);
    }
    cudaEventRecord(e_join, s2);

    // z chain (small) on the null stream
    {
        pack_nhwc<16, 16><<<64 * 16, 256>>>(z, zp16);
        pack_wT<<<(256 * 2304 + 255) / 256, 256>>>(w_z, wz16);
        conv3x3_bn_wmma<14, 14, 16, 16><<<dim3(98, 2), 128, SMEM_BYTES>>>(
            zp16, wz16, gamma_z, beta_z, mean_z, var_z, zfT);
    }

    // ---- join, then xcorr (17*16384 threads = 1088 blocks) ----
    cudaStreamWaitEvent(0, e_join, 0);
    xcorr_kernel<<<1088, 256>>>(zfT, xfT, out);
}